// round 1
// baseline (speedup 1.0000x reference)
#include <cuda_runtime.h>

#define NN    20000
#define EE    320000
#define E2T   340000          // EE + NN self loops
#define HIDC  256
#define NH    4
#define NEG   0.2f

// ---------------- device scratch (static, no allocation) ----------------
__device__ __align__(16) float g_xl[NN * HIDC];
__device__ __align__(16) float g_xr[NN * HIDC];
__device__ __align__(16) float g_h [NN * HIDC];
__device__ __align__(16) float g_ex[(size_t)E2T * NH];   // logits, then exp()
__device__ __align__(16) float g_m  [NN * NH];
__device__ __align__(16) float g_den[NN * NH];

__device__ __forceinline__ float lrelu(float x) { return x > 0.f ? x : NEG * x; }

__device__ __forceinline__ void atomicMaxF(float* addr, float v) {
    if (v >= 0.f) atomicMax((int*)addr, __float_as_int(v));
    else          atomicMin((unsigned int*)addr, __float_as_uint(v));
}

__device__ __forceinline__ void red_add_v4(float* p, float4 v) {
    asm volatile("red.global.add.v4.f32 [%0], {%1,%2,%3,%4};"
                 :: "l"(p), "f"(v.x), "f"(v.y), "f"(v.z), "f"(v.w) : "memory");
}

// ---------------- GEMM: C[M,256] = A[M,256] @ W[256,256] + bias ----------------
// 64x64 block tile, BK=16, 256 threads, 4x4 per thread.
__global__ void gemm_k(const float* __restrict__ Ain, int a_is_gh,
                       const float* __restrict__ W, const float* __restrict__ bias,
                       int c_sel) {
    const float* A = a_is_gh ? g_h : Ain;
    float*       C = c_sel ? g_xr : g_xl;
    const int M = NN;

    __shared__ float As[16][68];   // [k][m], row stride 272B (16B multiple)
    __shared__ float Bs[16][68];   // [k][n]

    int tid = threadIdx.x;
    int bm = blockIdx.x * 64;
    int bn = blockIdx.y * 64;
    int tx = tid & 15, ty = tid >> 4;

    int a_r  = tid >> 2;        // 0..63 row in tile
    int a_c4 = tid & 3;         // float4 within 16-wide K chunk
    int w_r  = tid >> 4;        // 0..15 k row
    int w_c4 = tid & 15;        // float4 within 64-wide N

    float acc[4][4] = {};

    for (int k0 = 0; k0 < 256; k0 += 16) {
        int gr = bm + a_r;
        float4 av = make_float4(0.f, 0.f, 0.f, 0.f);
        if (gr < M) av = *(const float4*)(A + (size_t)gr * 256 + k0 + a_c4 * 4);
        As[a_c4 * 4 + 0][a_r] = av.x;
        As[a_c4 * 4 + 1][a_r] = av.y;
        As[a_c4 * 4 + 2][a_r] = av.z;
        As[a_c4 * 4 + 3][a_r] = av.w;

        float4 wv = *(const float4*)(W + (size_t)(k0 + w_r) * 256 + bn + w_c4 * 4);
        *(float4*)&Bs[w_r][w_c4 * 4] = wv;

        __syncthreads();
        #pragma unroll
        for (int k = 0; k < 16; k++) {
            float4 a4 = *(float4*)&As[k][ty * 4];
            float4 b4 = *(float4*)&Bs[k][tx * 4];
            float a[4] = {a4.x, a4.y, a4.z, a4.w};
            float b[4] = {b4.x, b4.y, b4.z, b4.w};
            #pragma unroll
            for (int i = 0; i < 4; i++)
                #pragma unroll
                for (int j = 0; j < 4; j++)
                    acc[i][j] += a[i] * b[j];
        }
        __syncthreads();
    }

    float4 bv = *(const float4*)(bias + bn + tx * 4);
    #pragma unroll
    for (int i = 0; i < 4; i++) {
        int row = bm + ty * 4 + i;
        if (row < M) {
            float4 v = make_float4(acc[i][0] + bv.x, acc[i][1] + bv.y,
                                   acc[i][2] + bv.z, acc[i][3] + bv.w);
            *(float4*)(C + (size_t)row * 256 + bn + tx * 4) = v;
        }
    }
}

// ---------------- init kernels ----------------
__global__ void zero_k(float* dout, int to_gh) {
    int i = blockIdx.x * blockDim.x + threadIdx.x;
    if (i >= NN * HIDC / 4) return;
    float4* p = (float4*)(to_gh ? g_h : dout);
    p[i] = make_float4(0.f, 0.f, 0.f, 0.f);
}

__global__ void init_md_k() {
    int i = blockIdx.x * blockDim.x + threadIdx.x;
    if (i < NN * NH) {
        g_m[i]   = __int_as_float(0xff800000);  // -inf
        g_den[i] = 0.f;
    }
}

// ---------------- edge pass 1: logits + segment max ----------------
// one warp per edge; lane covers 8 channels; head = lane>>3
__global__ void edge_logits_k(const int* __restrict__ ei, const float* __restrict__ att) {
    int gw   = (blockIdx.x * blockDim.x + threadIdx.x) >> 5;
    int lane = threadIdx.x & 31;
    if (gw >= E2T) return;
    int src, dst;
    if (gw < EE) { src = ei[gw]; dst = ei[EE + gw]; }
    else         { src = gw - EE; dst = src; }

    int c0 = lane * 8;
    const float4* xl4 = (const float4*)(g_xl + (size_t)src * HIDC + c0);
    const float4* xr4 = (const float4*)(g_xr + (size_t)dst * HIDC + c0);
    float4 l0 = xl4[0], l1 = xl4[1];
    float4 r0 = xr4[0], r1 = xr4[1];

    int head = lane >> 3;
    const float4* a4 = (const float4*)(att + head * 64 + (lane & 7) * 8);
    float4 t0 = a4[0], t1 = a4[1];

    float s = t0.x * lrelu(l0.x + r0.x) + t0.y * lrelu(l0.y + r0.y)
            + t0.z * lrelu(l0.z + r0.z) + t0.w * lrelu(l0.w + r0.w)
            + t1.x * lrelu(l1.x + r1.x) + t1.y * lrelu(l1.y + r1.y)
            + t1.z * lrelu(l1.z + r1.z) + t1.w * lrelu(l1.w + r1.w);

    s += __shfl_down_sync(0xffffffffu, s, 4);
    s += __shfl_down_sync(0xffffffffu, s, 2);
    s += __shfl_down_sync(0xffffffffu, s, 1);

    if ((lane & 7) == 0) {
        g_ex[(size_t)gw * NH + head] = s;
        atomicMaxF(&g_m[dst * NH + head], s);
    }
}

// ---------------- edge pass 2: exp + segment sum ----------------
__global__ void edge_expsum_k(const int* __restrict__ ei) {
    int e = blockIdx.x * blockDim.x + threadIdx.x;
    if (e >= E2T) return;
    int dst = (e < EE) ? ei[EE + e] : e - EE;
    float4 lg = *(float4*)(g_ex + (size_t)e * 4);
    float4 mm = *(const float4*)(g_m + dst * 4);
    float4 v  = make_float4(expf(lg.x - mm.x), expf(lg.y - mm.y),
                            expf(lg.z - mm.z), expf(lg.w - mm.w));
    *(float4*)(g_ex + (size_t)e * 4) = v;
    red_add_v4(&g_den[dst * 4], v);
}

// ---------------- edge pass 3: weighted scatter-add aggregation ----------------
__global__ void edge_aggr_k(const int* __restrict__ ei, float* __restrict__ dout, int to_gh) {
    int gw   = (blockIdx.x * blockDim.x + threadIdx.x) >> 5;
    int lane = threadIdx.x & 31;
    if (gw >= E2T) return;
    int src, dst;
    if (gw < EE) { src = ei[gw]; dst = ei[EE + gw]; }
    else         { src = gw - EE; dst = src; }

    int head = lane >> 3;
    float alpha = g_ex[(size_t)gw * 4 + head] / g_den[dst * 4 + head];

    int c0 = lane * 8;
    const float4* xl4 = (const float4*)(g_xl + (size_t)src * HIDC + c0);
    float4 l0 = xl4[0], l1 = xl4[1];
    l0.x *= alpha; l0.y *= alpha; l0.z *= alpha; l0.w *= alpha;
    l1.x *= alpha; l1.y *= alpha; l1.z *= alpha; l1.w *= alpha;

    float* outp = (to_gh ? g_h : dout) + (size_t)dst * HIDC + c0;
    red_add_v4(outp, l0);
    red_add_v4(outp + 4, l1);
}

// ---------------- finalize: += bias, ReLU (in place) ----------------
__global__ void fin_k(float* dout, const float* __restrict__ bias, int to_gh) {
    int i = blockIdx.x * blockDim.x + threadIdx.x;
    if (i >= NN * HIDC / 4) return;
    float4* p = (float4*)(to_gh ? g_h : dout);
    float4 v = p[i];
    float4 b = ((const float4*)bias)[i & 63];
    v.x = fmaxf(v.x + b.x, 0.f);
    v.y = fmaxf(v.y + b.y, 0.f);
    v.z = fmaxf(v.z + b.z, 0.f);
    v.w = fmaxf(v.w + b.w, 0.f);
    p[i] = v;
}

// ---------------- host ----------------
extern "C" void kernel_launch(void* const* d_in, const int* in_sizes, int n_in,
                              void* d_out, int out_size) {
    const float* x     = (const float*)d_in[0];
    const int*   ei    = (const int*)  d_in[1];
    const float* Wl1   = (const float*)d_in[2];
    const float* bl1   = (const float*)d_in[3];
    const float* Wr1   = (const float*)d_in[4];
    const float* br1   = (const float*)d_in[5];
    const float* att1  = (const float*)d_in[6];
    const float* bias1 = (const float*)d_in[7];
    const float* Wl2   = (const float*)d_in[8];
    const float* bl2   = (const float*)d_in[9];
    const float* Wr2   = (const float*)d_in[10];
    const float* br2   = (const float*)d_in[11];
    const float* att2  = (const float*)d_in[12];
    const float* bias2 = (const float*)d_in[13];
    float* out = (float*)d_out;

    dim3 gg((NN + 63) / 64, 4);
    const int TB  = 256;
    const int zb  = (NN * HIDC / 4 + TB - 1) / TB;   // 5000
    const int mdb = (NN * NH + TB - 1) / TB;
    const int ewb = (E2T * 32 + TB - 1) / TB;        // warp-per-edge: 42500
    const int eb  = (E2T + TB - 1) / TB;

    // ----- layer 1 (input x, output -> g_h) -----
    gemm_k<<<gg, TB>>>(x, 0, Wl1, bl1, 0);
    gemm_k<<<gg, TB>>>(x, 0, Wr1, br1, 1);
    zero_k<<<zb, TB>>>(out, 1);
    init_md_k<<<mdb, TB>>>();
    edge_logits_k<<<ewb, TB>>>(ei, att1);
    edge_expsum_k<<<eb, TB>>>(ei);
    edge_aggr_k<<<ewb, TB>>>(ei, out, 1);
    fin_k<<<zb, TB>>>(out, bias1, 1);

    // ----- layer 2 (input g_h, output -> d_out) -----
    gemm_k<<<gg, TB>>>(x, 1, Wl2, bl2, 0);
    gemm_k<<<gg, TB>>>(x, 1, Wr2, br2, 1);
    zero_k<<<zb, TB>>>(out, 0);
    init_md_k<<<mdb, TB>>>();
    edge_logits_k<<<ewb, TB>>>(ei, att2);
    edge_expsum_k<<<eb, TB>>>(ei);
    edge_aggr_k<<<ewb, TB>>>(ei, out, 0);
    fin_k<<<zb, TB>>>(out, bias2, 0);
}